// round 15
// baseline (speedup 1.0000x reference)
#include <cuda_runtime.h>
#include <cstdint>

#define BB 8
#define CC 8
#define HH 512
#define WW 512
#define PLANE (HH*WW)                 // 262144
#define PIX   (BB*HH*WW)              // 2097152
#define NEL   (BB*CC*HH*WW)           // 16777216

#define TPB   128                     // 4 warps; 2 px/thread = 256-col half row
#define RPT   8                       // rows per thread
#define NBX   2
#define NBY   (HH/RPT)                // 64
#define NBLK  (NBX*NBY*BB)            // 1024

typedef unsigned long long u64;

__device__ double       g_acc;        // zero-init; reset by last block each run
__device__ unsigned int g_count;      // wraps to 0 via atomicInc

// sigmoid via single-MUFU tanh.approx: sigma(x) = 0.5 + 0.5*tanh(x/2)
__device__ __forceinline__ float sigt(float x) {
    float t;
    asm("tanh.approx.f32 %0, %1;" : "=f"(t) : "f"(0.5f * x));
    return fmaf(0.5f, t, 0.5f);
}
__device__ __forceinline__ float2 ld2(const float* __restrict__ p) {
    return *reinterpret_cast<const float2*>(p);
}
__device__ __forceinline__ float clog(float x) {
    return fmaxf(__logf(x), -100.0f);   // matches jnp.clip(log(x), -100)
}

// ---- packed f32x2 helpers (Blackwell FFMA2/FADD2/FMUL2 via PTX) ----
__device__ __forceinline__ u64 pk2(float lo, float hi) {
    u64 r; asm("mov.b64 %0, {%1, %2};" : "=l"(r) : "f"(lo), "f"(hi)); return r;
}
__device__ __forceinline__ void upk2(u64 x, float& lo, float& hi) {
    asm("mov.b64 {%0, %1}, %2;" : "=f"(lo), "=f"(hi) : "l"(x));
}
__device__ __forceinline__ u64 mul2(u64 a, u64 b) {
    u64 r; asm("mul.rn.f32x2 %0, %1, %2;" : "=l"(r) : "l"(a), "l"(b)); return r;
}
__device__ __forceinline__ u64 add2(u64 a, u64 b) {
    u64 r; asm("add.rn.f32x2 %0, %1, %2;" : "=l"(r) : "l"(a), "l"(b)); return r;
}
__device__ __forceinline__ u64 fma2_(u64 a, u64 b, u64 c) {
    u64 r; asm("fma.rn.f32x2 %0, %1, %2, %3;" : "=l"(r) : "l"(a), "l"(b), "l"(c));
    return r;
}
// load 2 px + sigmoid + pack
__device__ __forceinline__ u64 ldsig2(const float* __restrict__ p) {
    float2 x = ld2(p);
    return pk2(sigt(x.x), sigt(x.y));
}

// halo: value at col w0-1 (left lane's hi half); lane-0 fixup LDG
__device__ __forceinline__ float getLh(float ahi, const float* __restrict__ g,
                                       bool ok, int lane) {
    float v = __shfl_up_sync(0xffffffffu, ahi, 1);
    if (lane == 0) v = ok ? sigt(__ldg(g)) : 0.0f;
    return v;
}
// value at col w0+2 (right lane's lo half); lane-31 fixup LDG
__device__ __forceinline__ float getRh(float alo, const float* __restrict__ g,
                                       bool ok, int lane) {
    float v = __shfl_down_sync(0xffffffffu, alo, 1);
    if (lane == 31) v = ok ? sigt(__ldg(g)) : 0.0f;
    return v;
}

// con_target bitmasks (2 px x 8 bits) + 2 target bits packed into one u32
__device__ __forceinline__ unsigned build_mask(
        const float* __restrict__ cb, const float* __restrict__ tb) {
    unsigned m = 0;
#pragma unroll
    for (int c = 0; c < 8; c++) {
        float2 t = ld2(cb + c * PLANE);
        m |= ((unsigned)(t.x > 0.5f)) << c;
        m |= ((unsigned)(t.y > 0.5f)) << (8 + c);
    }
    float2 tg = ld2(tb);
    m |= ((unsigned)(tg.x > 0.5f)) << 16;
    m |= ((unsigned)(tg.y > 0.5f)) << 17;
    return m;
}

// votes + loss terms for one row of a packed 2-pixel strip of one branch.
// Sh: ch5,6,7 (row r-1), C: all 8 ch (row r), Sn: ch0,1,2 (row r+1), packed.
__device__ __forceinline__ float row_votes_pk(
    const u64 Sh[3], const u64 C[8], const u64 Sn[3],
    const float* __restrict__ px,
    bool wlo, bool whi, int lane, bool hmok, bool hpok,
    unsigned mp, const u64 c0[8], const u64 c1[8], int pass)
{
    // halves needed for halo packing
    float sh2lo, sh2hi, sh0lo, sh0hi, c4lo, c4hi, c3lo, c3hi;
    float sn2lo, sn2hi, sn0lo, sn0hi;
    upk2(Sh[2], sh2lo, sh2hi); upk2(Sh[0], sh0lo, sh0hi);
    upk2(C[4],  c4lo,  c4hi);  upk2(C[3],  c3lo,  c3hi);
    upk2(Sn[2], sn2lo, sn2hi); upk2(Sn[0], sn0lo, sn0hi);

    float L7 = getLh(sh2hi, px - WW + 7 * PLANE - 1, hmok && !wlo, lane);
    float R5 = getRh(sh0lo, px - WW + 5 * PLANE + 2, hmok && !whi, lane);
    float L4 = getLh(c4hi,  px      + 4 * PLANE - 1, !wlo,         lane);
    float R3 = getRh(c3lo,  px      + 3 * PLANE + 2, !whi,         lane);
    float L2 = getLh(sn2hi, px + WW + 2 * PLANE - 1, hpok && !wlo, lane);
    float R0 = getRh(sn0lo, px + WW + 0 * PLANE + 2, hpok && !whi, lane);

    u64 nb[8];
    nb[0] = pk2(L7, sh2lo);     // c7(r-1, w-1)
    nb[1] = Sh[1];              // c6(r-1, w)
    nb[2] = pk2(sh0hi, R5);     // c5(r-1, w+1)
    nb[3] = pk2(L4, c4lo);      // c4(r,   w-1)
    nb[4] = pk2(c3hi, R3);      // c3(r,   w+1)
    nb[5] = pk2(L2, sn2lo);     // c2(r+1, w-1)
    nb[6] = Sn[1];              // c1(r+1, w)
    nb[7] = pk2(sn0hi, R0);     // c0(r+1, w+1)

    const u64 one2 = pk2(1.0f, 1.0f);
    u64 glo = pk2(0.0f, 0.0f), pA = one2, pB = one2;
    u64 vv[8];
#pragma unroll
    for (int k = 0; k < 8; k++) {
        u64 v = mul2(C[k], nb[k]);
        vv[k] = v;
        glo = add2(glo, v);
        pA = mul2(pA, fma2_(v,    c1[k], c0[k]));   // t ? v : 1-v (exact)
        pB = mul2(pB, fma2_(C[k], c1[k], c0[k]));   // t ? s : 1-s (exact)
    }
    float mnp[2] = {1e30f, 1e30f};
    if (pass == 1) {
#pragma unroll
        for (int k = 0; k < 8; k++) {
            float a, b2; upk2(vv[k], a, b2);
            mnp[0] = fminf(mnp[0], a);
            mnp[1] = fminf(mnp[1], b2);
        }
    }

    float pa[2], pb[2], gg[2];
    upk2(pA, pa[0], pa[1]); upk2(pB, pb[0], pb[1]); upk2(glo, gg[0], gg[1]);

    float accb = 0.0f, accp = 0.0f;
#pragma unroll
    for (int p = 0; p < 2; p++) {
        unsigned m = (mp >> (8 * p)) & 0xFFu;
        bool T = (mp >> (16 + p)) & 1u;

        float bic, co;
        if (pa[p] >= 1e-37f) {
            bic = __logf(pa[p]);
        } else {                      // rare: border zeros / extreme tails
            bic = 0.0f;
#pragma unroll
            for (int k = 0; k < 8; k++) {
                float lo, hi; upk2(vv[k], lo, hi);
                float v = p ? hi : lo;
                bool t = (m >> k) & 1u;
                bic += clog(t ? v : 1.0f - v);
            }
        }
        if (pb[p] >= 1e-37f) {
            co = __logf(pb[p]);
        } else {
            co = 0.0f;
#pragma unroll
            for (int k = 0; k < 8; k++) {
                float lo, hi; upk2(C[k], lo, hi);
                float s = p ? hi : lo;
                bool t = (m >> k) & 1u;
                co += clog(t ? s : 1.0f - s);
            }
        }
        accb += 0.2f * bic + 0.8f * co;

        float g = gg[p] * 0.125f;
        float x;
        if (pass == 0) {
            x = T ? g : 1.0f - g;                        // bce_loss1
        } else {
            bool edge = (m != 0u) && (m != 255u);
            float de  = edge ? (1.0f - mnp[p]) : g;      // decouple map
            x = T ? de : 1.0f - de;
        }
        accp += clog(x);
    }
    return accb * (1.0f / (float)NEL) + accp * (1.0f / (float)PIX);
}

__global__ void __launch_bounds__(TPB, 4)
bicon_loss_kernel(const float* __restrict__ atts,
                  const float* __restrict__ dets,
                  const float* __restrict__ target,
                  const float* __restrict__ con,
                  float* __restrict__ out)
{
    __shared__ unsigned mk[RPT * TPB];   // 4 KB per-thread mask cache
    __shared__ float wsum[TPB / 32];

    const int tid  = threadIdx.x;
    const int lane = tid & 31;
    const int bid  = blockIdx.x;
    const int cpart = bid & (NBX - 1);
    const int band  = (bid / NBX) & (NBY - 1);
    const int b     = bid / (NBX * NBY);
    const int w0 = cpart * (TPB * 2) + tid * 2;
    const int r0 = band * RPT;
    const bool wlo = (w0 == 0), whi = (w0 + 2 == WW);

    const size_t bst  = (size_t)CC * PLANE;
    const size_t soff = (size_t)r0 * WW + w0;

    float contrib = 0.0f;

#pragma unroll 1
    for (int pass = 0; pass < 2; pass++) {
        const float* px = (pass ? dets : atts) + (size_t)b * bst + soff;

        // prologue: row r0-1 ch5..7 (or zeros), row r0 all 8 — packed
        u64 Sh[3], C[8];
        if (r0 > 0) {
#pragma unroll
            for (int j = 0; j < 3; j++) Sh[j] = ldsig2(px - WW + (5 + j) * PLANE);
        } else {
#pragma unroll
            for (int j = 0; j < 3; j++) Sh[j] = 0ull;
        }
#pragma unroll
        for (int c = 0; c < 8; c++) C[c] = ldsig2(px + c * PLANE);

        const float* cpx = con + (size_t)b * bst + soff;       // rolling ptrs
        const float* tpx = target + (size_t)b * PLANE + soff;

#pragma unroll 1
        for (int i = 0; i < RPT - 1; i++) {
            const int r = r0 + i;
            unsigned mp;
            if (pass == 0) {
                mp = build_mask(cpx, tpx);
                mk[i * TPB + tid] = mp;          // private slot, no barrier
            } else {
                mp = mk[i * TPB + tid];
            }
            // packed select constants for this row (both pixels)
            u64 c0[8], c1[8];
#pragma unroll
            for (int k = 0; k < 8; k++) {
                bool t0 = (mp >> k) & 1u, t1 = (mp >> (8 + k)) & 1u;
                c1[k] = pk2(t0 ? 1.0f : -1.0f, t1 ? 1.0f : -1.0f);
                c0[k] = pk2(t0 ? 0.0f :  1.0f, t1 ? 0.0f :  1.0f);
            }
            // full next-row prefetch (8 independent LDG.64)
            u64 N[8];
#pragma unroll
            for (int c = 0; c < 8; c++) N[c] = ldsig2(px + WW + c * PLANE);

            contrib += row_votes_pk(Sh, C, N, px, wlo, whi, lane,
                                    r > 0, true, mp, c0, c1, pass);
            // roll (u64 moves)
#pragma unroll
            for (int j = 0; j < 3; j++) Sh[j] = C[5 + j];
#pragma unroll
            for (int c = 0; c < 8; c++) C[c] = N[c];
            px += WW; cpx += WW; tpx += WW;
        }
        {   // last row of band: next row needs only ch0..2
            const int r = r0 + RPT - 1;
            unsigned mp;
            if (pass == 0) {
                mp = build_mask(cpx, tpx);
                mk[(RPT - 1) * TPB + tid] = mp;
            } else {
                mp = mk[(RPT - 1) * TPB + tid];
            }
            u64 c0[8], c1[8];
#pragma unroll
            for (int k = 0; k < 8; k++) {
                bool t0 = (mp >> k) & 1u, t1 = (mp >> (8 + k)) & 1u;
                c1[k] = pk2(t0 ? 1.0f : -1.0f, t1 ? 1.0f : -1.0f);
                c0[k] = pk2(t0 ? 0.0f :  1.0f, t1 ? 0.0f :  1.0f);
            }
            const bool hpok = (r + 1 < HH);
            u64 Sn[3];
            if (hpok) {
#pragma unroll
                for (int c = 0; c < 3; c++) Sn[c] = ldsig2(px + WW + c * PLANE);
            } else {
#pragma unroll
                for (int c = 0; c < 3; c++) Sn[c] = 0ull;
            }
            contrib += row_votes_pk(Sh, C, Sn, px, wlo, whi, lane,
                                    true, hpok, mp, c0, c1, pass);
        }
    }

    // block reduction: warp shfl -> smem -> one double atomic per block
#pragma unroll
    for (int o = 16; o > 0; o >>= 1)
        contrib += __shfl_down_sync(0xFFFFFFFFu, contrib, o);
    if (lane == 0) wsum[tid >> 5] = contrib;
    __syncthreads();

    if (tid == 0) {
        float s = 0.0f;
#pragma unroll
        for (int i = 0; i < TPB / 32; i++) s += wsum[i];
        atomicAdd(&g_acc, (double)s);
        __threadfence();
        unsigned old = atomicInc(&g_count, NBLK - 1u);   // wraps to 0 on last
        if (old == NBLK - 1u) {
            unsigned long long raw =
                atomicExch((unsigned long long*)&g_acc, 0ULL);
            out[0] = -(float)__longlong_as_double(raw);
        }
    }
}

extern "C" void kernel_launch(void* const* d_in, const int* in_sizes, int n_in,
                              void* d_out, int out_size) {
    const float* atts   = (const float*)d_in[0];
    const float* dets   = (const float*)d_in[1];
    const float* target = (const float*)d_in[2];
    const float* con    = (const float*)d_in[3];
    float* out = (float*)d_out;

    bicon_loss_kernel<<<NBLK, TPB>>>(atts, dets, target, con, out);
}

// round 16
// speedup vs baseline: 1.4591x; 1.4591x over previous
#include <cuda_runtime.h>
#include <cstdint>

#define BB 8
#define CC 8
#define HH 512
#define WW 512
#define PLANE (HH*WW)                 // 262144
#define PIX   (BB*HH*WW)              // 2097152
#define NEL   (BB*CC*HH*WW)           // 16777216

#define TPB   64                      // threads per block (2 warps)
#define RPT   8                       // rows per thread
#define CPB   (TPB*4)                 // 256 cols per block
#define NBX   (WW/CPB)                // 2
#define NBY   (HH/RPT)                // 64
#define NBLK  (NBX*NBY*BB)            // 1024

__device__ double       g_acc;        // zero-init; reset by last block each run
__device__ unsigned int g_count;      // wraps to 0 via atomicInc

// sigmoid via single-MUFU tanh.approx: sigma(x) = 0.5 + 0.5*tanh(x/2)
__device__ __forceinline__ float sigt(float x) {
    float t;
    asm("tanh.approx.f32 %0, %1;" : "=f"(t) : "f"(0.5f * x));
    return fmaf(0.5f, t, 0.5f);
}
__device__ __forceinline__ float4 ld4(const float* __restrict__ p) {
    return *reinterpret_cast<const float4*>(p);
}
__device__ __forceinline__ float clog(float x) {
    return fmaxf(__logf(x), -100.0f);   // matches jnp.clip(log(x), -100)
}

// col w0-1 of same row/channel: left lane's a[3]; lane-0 fixup LDG
__device__ __forceinline__ float getL(const float a[4], const float* __restrict__ g,
                                      bool ok, int lane) {
    float v = __shfl_up_sync(0xffffffffu, a[3], 1);
    if (lane == 0) v = ok ? sigt(__ldg(g)) : 0.0f;
    return v;
}
// col w0+4: right lane's a[0]; lane-31 fixup LDG
__device__ __forceinline__ float getR(const float a[4], const float* __restrict__ g,
                                      bool ok, int lane) {
    float v = __shfl_down_sync(0xffffffffu, a[0], 1);
    if (lane == 31) v = ok ? sigt(__ldg(g)) : 0.0f;
    return v;
}

// con_target bitmasks (4 px x 8 bits) + target bits packed into one u64
__device__ __forceinline__ unsigned long long build_mask(
        const float* __restrict__ cb, const float* __restrict__ tb) {
    unsigned m0 = 0, m1 = 0, m2 = 0, m3 = 0;
#pragma unroll
    for (int c = 0; c < 8; c++) {
        float4 t = ld4(cb + c * PLANE);
        m0 |= ((unsigned)(t.x > 0.5f)) << c;
        m1 |= ((unsigned)(t.y > 0.5f)) << c;
        m2 |= ((unsigned)(t.z > 0.5f)) << c;
        m3 |= ((unsigned)(t.w > 0.5f)) << c;
    }
    float4 tg = ld4(tb);
    unsigned t4 = (unsigned)(tg.x > 0.5f) | ((unsigned)(tg.y > 0.5f) << 1)
                | ((unsigned)(tg.z > 0.5f) << 2) | ((unsigned)(tg.w > 0.5f) << 3);
    return (unsigned long long)(m0 | (m1 << 8) | (m2 << 16) | (m3 << 24))
         | ((unsigned long long)t4 << 32);
}

// votes + loss terms for one row of a 4-pixel strip.
// Shm: ch5,6,7 sigmoids at row r-1; C: all 8 ch at row r; Sn: ch0,1,2 at row r+1.
__device__ __forceinline__ float row_votes(
    const float Shm[3][4], const float C[8][4], const float Sn[3][4],
    const float* __restrict__ xb, int r, int w0,
    bool wlo, bool whi, int lane, bool hmok, bool hpok,
    unsigned long long mp, int pass)
{
    const float* rm = xb + (r - 1) * WW + w0;
    const float* rc = xb + r * WW + w0;
    const float* rp = xb + (r + 1) * WW + w0;

    float L7 = getL(Shm[2], rm + 7 * PLANE - 1, hmok && !wlo, lane);
    float R5 = getR(Shm[0], rm + 5 * PLANE + 4, hmok && !whi, lane);
    float L4 = getL(C[4],   rc + 4 * PLANE - 1, !wlo,         lane);
    float R3 = getR(C[3],   rc + 3 * PLANE + 4, !whi,         lane);
    float L2 = getL(Sn[2],  rp + 2 * PLANE - 1, hpok && !wlo, lane);
    float R0 = getR(Sn[0],  rp + 0 * PLANE + 4, hpok && !whi, lane);

    float accb = 0.0f, accp = 0.0f;
#pragma unroll
    for (int p = 0; p < 4; p++) {
        float nb[8];
        nb[0] = (p == 0) ? L7 : Shm[2][p == 0 ? 0 : p - 1];   // c7(r-1, w-1)
        nb[1] = Shm[1][p];                                    // c6(r-1, w)
        nb[2] = (p == 3) ? R5 : Shm[0][p == 3 ? 3 : p + 1];   // c5(r-1, w+1)
        nb[3] = (p == 0) ? L4 : C[4][p == 0 ? 0 : p - 1];     // c4(r,   w-1)
        nb[4] = (p == 3) ? R3 : C[3][p == 3 ? 3 : p + 1];     // c3(r,   w+1)
        nb[5] = (p == 0) ? L2 : Sn[2][p == 0 ? 0 : p - 1];    // c2(r+1, w-1)
        nb[6] = Sn[1][p];                                     // c1(r+1, w)
        nb[7] = (p == 3) ? R0 : Sn[0][p == 3 ? 3 : p + 1];    // c0(r+1, w+1)

        unsigned m = (unsigned)(mp >> (8 * p)) & 0xFFu;
        bool T = (mp >> (32 + p)) & 1ull;

        float pA0 = 1.f, pA1 = 1.f, pB0 = 1.f, pB1 = 1.f;
        float glo = 0.f, mn = 1e30f;
        int npen = 0;
#pragma unroll
        for (int k = 0; k < 8; k++) {
            float s = C[k][p];
            float v = s * nb[k];
            glo += v;
            mn = fminf(mn, v);
            bool t = (m >> k) & 1u;
            float A = t ? v : 1.0f - v;
            if (A == 0.0f) { npen++; A = 1.0f; }   // padded border: exact -100 later
            float Bv = t ? s : 1.0f - s;
            if (k < 4) { pA0 *= A; pB0 *= Bv; }
            else       { pA1 *= A; pB1 *= Bv; }
        }
        float bic = __logf(pA0) + __logf(pA1) - 100.0f * (float)npen;
        float co  = __logf(pB0) + __logf(pB1);
        accb += 0.2f * bic + 0.8f * co;

        float g = glo * 0.125f;
        float x;
        if (pass == 0) {
            x = T ? g : 1.0f - g;                        // bce_loss1
        } else {
            bool edge = (m != 0u) && (m != 255u);
            float de  = edge ? (1.0f - mn) : g;          // decouple map
            x = T ? de : 1.0f - de;
        }
        accp += clog(x);
    }
    return accb * (1.0f / (float)NEL) + accp * (1.0f / (float)PIX);
}

__global__ void __launch_bounds__(TPB, 7)
bicon_loss_kernel(const float* __restrict__ atts,
                  const float* __restrict__ dets,
                  const float* __restrict__ target,
                  const float* __restrict__ con,
                  float* __restrict__ out)
{
    __shared__ unsigned long long mk[RPT * TPB];   // 4 KB per-thread mask cache
    __shared__ float wsum[TPB / 32];

    const int tid  = threadIdx.x;
    const int lane = tid & 31;
    const int bid  = blockIdx.x;
    const int cpart = bid & (NBX - 1);
    const int band  = (bid / NBX) & (NBY - 1);
    const int b     = bid / (NBX * NBY);
    const int w0 = cpart * CPB + tid * 4;
    const int r0 = band * RPT;
    const bool wlo = (w0 == 0), whi = (w0 + 4 == WW);

    const size_t bst = (size_t)CC * PLANE;
    const float* cb0 = con + (size_t)b * bst;
    const float* tb0 = target + (size_t)b * PLANE;

    float contrib = 0.0f;

#pragma unroll
    for (int pass = 0; pass < 2; pass++) {
        const float* xb = (pass ? dets : atts) + (size_t)b * bst;

        // prologue: row r0-1 channels 5,6,7; row r0 full
        float Shm[3][4];
        if (r0 > 0) {
            const float* pm = xb + (r0 - 1) * WW + w0;
#pragma unroll
            for (int j = 0; j < 3; j++) {
                float4 x = ld4(pm + (5 + j) * PLANE);
                Shm[j][0] = sigt(x.x); Shm[j][1] = sigt(x.y);
                Shm[j][2] = sigt(x.z); Shm[j][3] = sigt(x.w);
            }
        } else {
#pragma unroll
            for (int j = 0; j < 3; j++)
#pragma unroll
                for (int p = 0; p < 4; p++) Shm[j][p] = 0.0f;
        }
        float C[8][4];
        {
            const float* pc = xb + r0 * WW + w0;
#pragma unroll
            for (int c = 0; c < 8; c++) {
                float4 x = ld4(pc + c * PLANE);
                C[c][0] = sigt(x.x); C[c][1] = sigt(x.y);
                C[c][2] = sigt(x.z); C[c][3] = sigt(x.w);
            }
        }

#pragma unroll 1
        for (int i = 0; i < RPT - 1; i++) {
            const int r = r0 + i;
            unsigned long long mp;
            if (pass == 0) {
                mp = build_mask(cb0 + r * WW + w0, tb0 + r * WW + w0);
                mk[i * TPB + tid] = mp;
            } else {
                mp = mk[i * TPB + tid];
            }
            float N[8][4];
#pragma unroll
            for (int c = 0; c < 8; c++) {
                float4 x = ld4(xb + (r + 1) * WW + w0 + c * PLANE);
                N[c][0] = sigt(x.x); N[c][1] = sigt(x.y);
                N[c][2] = sigt(x.z); N[c][3] = sigt(x.w);
            }

            contrib += row_votes(Shm, C, N, xb, r, w0, wlo, whi, lane,
                                 r > 0, true, mp, pass);
            // roll
#pragma unroll
            for (int j = 0; j < 3; j++)
#pragma unroll
                for (int p = 0; p < 4; p++) Shm[j][p] = C[5 + j][p];
#pragma unroll
            for (int c = 0; c < 8; c++)
#pragma unroll
                for (int p = 0; p < 4; p++) C[c][p] = N[c][p];
        }
        {   // last row of band: next row needs only channels 0,1,2
            const int r = r0 + RPT - 1;
            unsigned long long mp;
            if (pass == 0) {
                mp = build_mask(cb0 + r * WW + w0, tb0 + r * WW + w0);
                mk[(RPT - 1) * TPB + tid] = mp;
            } else {
                mp = mk[(RPT - 1) * TPB + tid];
            }
            const bool hpok = (r + 1 < HH);
            float Sn[3][4];
            if (hpok) {
                const float* pp = xb + (r + 1) * WW + w0;
#pragma unroll
                for (int c = 0; c < 3; c++) {
                    float4 x = ld4(pp + c * PLANE);
                    Sn[c][0] = sigt(x.x); Sn[c][1] = sigt(x.y);
                    Sn[c][2] = sigt(x.z); Sn[c][3] = sigt(x.w);
                }
            } else {
#pragma unroll
                for (int c = 0; c < 3; c++)
#pragma unroll
                    for (int p = 0; p < 4; p++) Sn[c][p] = 0.0f;
            }
            contrib += row_votes(Shm, C, Sn, xb, r, w0, wlo, whi, lane,
                                 true, hpok, mp, pass);
        }
    }

    // block reduction: warp shfl -> smem -> one double atomic per block
#pragma unroll
    for (int o = 16; o > 0; o >>= 1)
        contrib += __shfl_down_sync(0xFFFFFFFFu, contrib, o);
    if (lane == 0) wsum[tid >> 5] = contrib;
    __syncthreads();

    if (tid == 0) {
        float s = 0.0f;
#pragma unroll
        for (int i = 0; i < TPB / 32; i++) s += wsum[i];
        atomicAdd(&g_acc, (double)s);
        __threadfence();
        unsigned old = atomicInc(&g_count, NBLK - 1u);   // wraps to 0 on last
        if (old == NBLK - 1u) {
            unsigned long long raw =
                atomicExch((unsigned long long*)&g_acc, 0ULL);
            out[0] = -(float)__longlong_as_double(raw);
        }
    }
}

extern "C" void kernel_launch(void* const* d_in, const int* in_sizes, int n_in,
                              void* d_out, int out_size) {
    const float* atts   = (const float*)d_in[0];
    const float* dets   = (const float*)d_in[1];
    const float* target = (const float*)d_in[2];
    const float* con    = (const float*)d_in[3];
    float* out = (float*)d_out;

    bicon_loss_kernel<<<NBLK, TPB>>>(atts, dets, target, con, out);
}

// round 17
// speedup vs baseline: 1.4599x; 1.0006x over previous
#include <cuda_runtime.h>
#include <cstdint>

#define BB 8
#define CC 8
#define HH 512
#define WW 512
#define PLANE (HH*WW)                 // 262144
#define PIX   (BB*HH*WW)              // 2097152
#define NEL   (BB*CC*HH*WW)           // 16777216

#define TPB   64                      // threads per block (2 warps)
#define RPT   8                       // rows per thread
#define CPB   (TPB*4)                 // 256 cols per block
#define NBX   (WW/CPB)                // 2
#define NBY   (HH/RPT)                // 64
#define NBLK  (NBX*NBY*BB)            // 1024

__device__ double       g_acc;        // zero-init; reset by last block each run
__device__ unsigned int g_count;      // wraps to 0 via atomicInc

// sigmoid via single-MUFU tanh.approx: sigma(x) = 0.5 + 0.5*tanh(x/2)
__device__ __forceinline__ float sigt(float x) {
    float t;
    asm("tanh.approx.f32 %0, %1;" : "=f"(t) : "f"(0.5f * x));
    return fmaf(0.5f, t, 0.5f);
}
__device__ __forceinline__ float4 ld4(const float* __restrict__ p) {
    return *reinterpret_cast<const float4*>(p);
}
__device__ __forceinline__ float clog(float x) {
    return fmaxf(__logf(x), -100.0f);   // matches jnp.clip(log(x), -100)
}

// col w0-1 of same row/channel: left lane's a[3]; lane-0 fixup LDG
__device__ __forceinline__ float getL(const float a[4], const float* __restrict__ g,
                                      bool ok, int lane) {
    float v = __shfl_up_sync(0xffffffffu, a[3], 1);
    if (lane == 0) v = ok ? sigt(__ldg(g)) : 0.0f;
    return v;
}
// col w0+4: right lane's a[0]; lane-31 fixup LDG
__device__ __forceinline__ float getR(const float a[4], const float* __restrict__ g,
                                      bool ok, int lane) {
    float v = __shfl_down_sync(0xffffffffu, a[0], 1);
    if (lane == 31) v = ok ? sigt(__ldg(g)) : 0.0f;
    return v;
}

// con_target bitmasks (4 px x 8 bits) + target bits packed into one u64
__device__ __forceinline__ unsigned long long build_mask(
        const float* __restrict__ cb, const float* __restrict__ tb) {
    unsigned m0 = 0, m1 = 0, m2 = 0, m3 = 0;
#pragma unroll
    for (int c = 0; c < 8; c++) {
        float4 t = ld4(cb + c * PLANE);
        m0 |= ((unsigned)(t.x > 0.5f)) << c;
        m1 |= ((unsigned)(t.y > 0.5f)) << c;
        m2 |= ((unsigned)(t.z > 0.5f)) << c;
        m3 |= ((unsigned)(t.w > 0.5f)) << c;
    }
    float4 tg = ld4(tb);
    unsigned t4 = (unsigned)(tg.x > 0.5f) | ((unsigned)(tg.y > 0.5f) << 1)
                | ((unsigned)(tg.z > 0.5f) << 2) | ((unsigned)(tg.w > 0.5f) << 3);
    return (unsigned long long)(m0 | (m1 << 8) | (m2 << 16) | (m3 << 24))
         | ((unsigned long long)t4 << 32);
}

// votes + loss terms for one row of a 4-pixel strip. PASS is compile-time:
// pass-0 instances drop the vote-min chain entirely (only pass 1 needs it).
// Shm: ch5,6,7 sigmoids at row r-1; C: all 8 ch at row r; Sn: ch0,1,2 at row r+1.
template <int PASS>
__device__ __forceinline__ float row_votes(
    const float Shm[3][4], const float C[8][4], const float Sn[3][4],
    const float* __restrict__ xb, int r, int w0,
    bool wlo, bool whi, int lane, bool hmok, bool hpok,
    unsigned long long mp)
{
    const float* rm = xb + (r - 1) * WW + w0;
    const float* rc = xb + r * WW + w0;
    const float* rp = xb + (r + 1) * WW + w0;

    float L7 = getL(Shm[2], rm + 7 * PLANE - 1, hmok && !wlo, lane);
    float R5 = getR(Shm[0], rm + 5 * PLANE + 4, hmok && !whi, lane);
    float L4 = getL(C[4],   rc + 4 * PLANE - 1, !wlo,         lane);
    float R3 = getR(C[3],   rc + 3 * PLANE + 4, !whi,         lane);
    float L2 = getL(Sn[2],  rp + 2 * PLANE - 1, hpok && !wlo, lane);
    float R0 = getR(Sn[0],  rp + 0 * PLANE + 4, hpok && !whi, lane);

    float accb = 0.0f, accp = 0.0f;
#pragma unroll
    for (int p = 0; p < 4; p++) {
        float nb[8];
        nb[0] = (p == 0) ? L7 : Shm[2][p == 0 ? 0 : p - 1];   // c7(r-1, w-1)
        nb[1] = Shm[1][p];                                    // c6(r-1, w)
        nb[2] = (p == 3) ? R5 : Shm[0][p == 3 ? 3 : p + 1];   // c5(r-1, w+1)
        nb[3] = (p == 0) ? L4 : C[4][p == 0 ? 0 : p - 1];     // c4(r,   w-1)
        nb[4] = (p == 3) ? R3 : C[3][p == 3 ? 3 : p + 1];     // c3(r,   w+1)
        nb[5] = (p == 0) ? L2 : Sn[2][p == 0 ? 0 : p - 1];    // c2(r+1, w-1)
        nb[6] = Sn[1][p];                                     // c1(r+1, w)
        nb[7] = (p == 3) ? R0 : Sn[0][p == 3 ? 3 : p + 1];    // c0(r+1, w+1)

        unsigned m = (unsigned)(mp >> (8 * p)) & 0xFFu;
        bool T = (mp >> (32 + p)) & 1ull;

        float pA0 = 1.f, pA1 = 1.f, pB0 = 1.f, pB1 = 1.f;
        float glo = 0.f, mn = 1e30f;
        int npen = 0;
#pragma unroll
        for (int k = 0; k < 8; k++) {
            float s = C[k][p];
            float v = s * nb[k];
            glo += v;
            if (PASS == 1) mn = fminf(mn, v);   // only decouple map needs min
            bool t = (m >> k) & 1u;
            float A = t ? v : 1.0f - v;
            if (A == 0.0f) { npen++; A = 1.0f; }   // padded border: exact -100 later
            float Bv = t ? s : 1.0f - s;
            if (k < 4) { pA0 *= A; pB0 *= Bv; }
            else       { pA1 *= A; pB1 *= Bv; }
        }
        float bic = __logf(pA0) + __logf(pA1) - 100.0f * (float)npen;
        float co  = __logf(pB0) + __logf(pB1);
        accb += 0.2f * bic + 0.8f * co;

        float g = glo * 0.125f;
        float x;
        if (PASS == 0) {
            x = T ? g : 1.0f - g;                        // bce_loss1
        } else {
            bool edge = (m != 0u) && (m != 255u);
            float de  = edge ? (1.0f - mn) : g;          // decouple map
            x = T ? de : 1.0f - de;
        }
        accp += clog(x);
    }
    return accb * (1.0f / (float)NEL) + accp * (1.0f / (float)PIX);
}

// one branch (atts or dets) over the band; PASS selects loss semantics and
// whether masks are built (pass 0) or replayed from smem (pass 1).
template <int PASS>
__device__ __forceinline__ float run_branch(
    const float* __restrict__ xb, const float* __restrict__ cb0,
    const float* __restrict__ tb0, unsigned long long* __restrict__ mk,
    int tid, int lane, int r0, int w0, bool wlo, bool whi)
{
    float contrib = 0.0f;

    // prologue: row r0-1 channels 5,6,7; row r0 full
    float Shm[3][4];
    if (r0 > 0) {
        const float* pm = xb + (r0 - 1) * WW + w0;
#pragma unroll
        for (int j = 0; j < 3; j++) {
            float4 x = ld4(pm + (5 + j) * PLANE);
            Shm[j][0] = sigt(x.x); Shm[j][1] = sigt(x.y);
            Shm[j][2] = sigt(x.z); Shm[j][3] = sigt(x.w);
        }
    } else {
#pragma unroll
        for (int j = 0; j < 3; j++)
#pragma unroll
            for (int p = 0; p < 4; p++) Shm[j][p] = 0.0f;
    }
    float C[8][4];
    {
        const float* pc = xb + r0 * WW + w0;
#pragma unroll
        for (int c = 0; c < 8; c++) {
            float4 x = ld4(pc + c * PLANE);
            C[c][0] = sigt(x.x); C[c][1] = sigt(x.y);
            C[c][2] = sigt(x.z); C[c][3] = sigt(x.w);
        }
    }

#pragma unroll 1
    for (int i = 0; i < RPT - 1; i++) {
        const int r = r0 + i;
        unsigned long long mp;
        if (PASS == 0) {
            mp = build_mask(cb0 + r * WW + w0, tb0 + r * WW + w0);
            mk[i * TPB + tid] = mp;              // private slot, no barrier needed
        } else {
            mp = mk[i * TPB + tid];
        }
        float N[8][4];                           // full next-row prefetch burst
#pragma unroll
        for (int c = 0; c < 8; c++) {
            float4 x = ld4(xb + (r + 1) * WW + w0 + c * PLANE);
            N[c][0] = sigt(x.x); N[c][1] = sigt(x.y);
            N[c][2] = sigt(x.z); N[c][3] = sigt(x.w);
        }

        contrib += row_votes<PASS>(Shm, C, N, xb, r, w0, wlo, whi, lane,
                                   r > 0, true, mp);
        // roll
#pragma unroll
        for (int j = 0; j < 3; j++)
#pragma unroll
            for (int p = 0; p < 4; p++) Shm[j][p] = C[5 + j][p];
#pragma unroll
        for (int c = 0; c < 8; c++)
#pragma unroll
            for (int p = 0; p < 4; p++) C[c][p] = N[c][p];
    }
    {   // last row of band: next row needs only channels 0,1,2
        const int r = r0 + RPT - 1;
        unsigned long long mp;
        if (PASS == 0) {
            mp = build_mask(cb0 + r * WW + w0, tb0 + r * WW + w0);
            mk[(RPT - 1) * TPB + tid] = mp;
        } else {
            mp = mk[(RPT - 1) * TPB + tid];
        }
        const bool hpok = (r + 1 < HH);
        float Sn[3][4];
        if (hpok) {
            const float* pp = xb + (r + 1) * WW + w0;
#pragma unroll
            for (int c = 0; c < 3; c++) {
                float4 x = ld4(pp + c * PLANE);
                Sn[c][0] = sigt(x.x); Sn[c][1] = sigt(x.y);
                Sn[c][2] = sigt(x.z); Sn[c][3] = sigt(x.w);
            }
        } else {
#pragma unroll
            for (int c = 0; c < 3; c++)
#pragma unroll
                for (int p = 0; p < 4; p++) Sn[c][p] = 0.0f;
        }
        contrib += row_votes<PASS>(Shm, C, Sn, xb, r, w0, wlo, whi, lane,
                                   true, hpok, mp);
    }
    return contrib;
}

__global__ void __launch_bounds__(TPB, 7)
bicon_loss_kernel(const float* __restrict__ atts,
                  const float* __restrict__ dets,
                  const float* __restrict__ target,
                  const float* __restrict__ con,
                  float* __restrict__ out)
{
    __shared__ unsigned long long mk[RPT * TPB];   // 4 KB per-thread mask cache
    __shared__ float wsum[TPB / 32];

    const int tid  = threadIdx.x;
    const int lane = tid & 31;
    const int bid  = blockIdx.x;
    const int cpart = bid & (NBX - 1);
    const int band  = (bid / NBX) & (NBY - 1);
    const int b     = bid / (NBX * NBY);
    const int w0 = cpart * CPB + tid * 4;
    const int r0 = band * RPT;
    const bool wlo = (w0 == 0), whi = (w0 + 4 == WW);

    const size_t bst = (size_t)CC * PLANE;
    const float* cb0 = con + (size_t)b * bst;
    const float* tb0 = target + (size_t)b * PLANE;

    float contrib =
        run_branch<0>(atts + (size_t)b * bst, cb0, tb0, mk,
                      tid, lane, r0, w0, wlo, whi)
      + run_branch<1>(dets + (size_t)b * bst, cb0, tb0, mk,
                      tid, lane, r0, w0, wlo, whi);

    // block reduction: warp shfl -> smem -> one double atomic per block
#pragma unroll
    for (int o = 16; o > 0; o >>= 1)
        contrib += __shfl_down_sync(0xFFFFFFFFu, contrib, o);
    if (lane == 0) wsum[tid >> 5] = contrib;
    __syncthreads();

    if (tid == 0) {
        float s = 0.0f;
#pragma unroll
        for (int i = 0; i < TPB / 32; i++) s += wsum[i];
        atomicAdd(&g_acc, (double)s);
        __threadfence();
        unsigned old = atomicInc(&g_count, NBLK - 1u);   // wraps to 0 on last
        if (old == NBLK - 1u) {
            unsigned long long raw =
                atomicExch((unsigned long long*)&g_acc, 0ULL);
            out[0] = -(float)__longlong_as_double(raw);
        }
    }
}

extern "C" void kernel_launch(void* const* d_in, const int* in_sizes, int n_in,
                              void* d_out, int out_size) {
    const float* atts   = (const float*)d_in[0];
    const float* dets   = (const float*)d_in[1];
    const float* target = (const float*)d_in[2];
    const float* con    = (const float*)d_in[3];
    float* out = (float*)d_out;

    bicon_loss_kernel<<<NBLK, TPB>>>(atts, dets, target, con, out);
}